// round 15
// baseline (speedup 1.0000x reference)
#include <cuda_runtime.h>
#include <math.h>

#define D_MODEL 256
#define N_STATE 64
#define LSEQ    2048
#define L2X     4096
#define NBATCH  16

typedef unsigned long long ull;

// Scratch (no cudaMalloc allowed).
__device__ float2 g_at[D_MODEL * LSEQ];   // 4 MB
// g_kf stored POSITION-ORDERED: g_kf[d*4096 + p] = Kf[rev16(p)] / 4096
__device__ float2 g_kf[D_MODEL * L2X];    // 8 MB

static __device__ __forceinline__ float2 cmul(float2 a, float2 b) {
    return make_float2(a.x * b.x - a.y * b.y, a.x * b.y + a.y * b.x);
}
static __device__ __forceinline__ float2 cadd(float2 a, float2 b) {
    return make_float2(a.x + b.x, a.y + b.y);
}
static __device__ __forceinline__ float2 csub(float2 a, float2 b) {
    return make_float2(a.x - b.x, a.y - b.y);
}

static __device__ __forceinline__ void barsync(int id, int nthr) {
    asm volatile("bar.sync %0, %1;" :: "r"(id), "r"(nthr) : "memory");
}

// packed f32x2 ops (sm_103a; FFMA2 only reachable via PTX)
#define F2ADD(d,a,b)   asm("add.rn.f32x2 %0,%1,%2;"    : "=l"(d) : "l"(a), "l"(b))
#define F2MUL(d,a,b)   asm("mul.rn.f32x2 %0,%1,%2;"    : "=l"(d) : "l"(a), "l"(b))
#define F2FMA(d,a,b,c) asm("fma.rn.f32x2 %0,%1,%2,%3;" : "=l"(d) : "l"(a), "l"(b), "l"(c))
#define F2PACK(d,lo,hi) asm("mov.b64 %0,{%1,%2};" : "=l"(d) : "f"(lo), "f"(hi))
#define F2UNPK(lo,hi,v) asm("mov.b64 {%0,%1},%2;" : "=f"(lo), "=f"(hi) : "l"(v))
#define FRCP(d,a)      asm("rcp.approx.f32 %0,%1;" : "=f"(d) : "f"(a))

// Triple-pad smem addressing: conflict-free for strides 256, 16, 1.
#define PIDX(a) ((a) + ((a) >> 4) + ((a) >> 8))

// radix-16 digit reversal for N=4096 (digits 16,16,16)
static __device__ __forceinline__ int rev16(int k) {
    return ((k & 15) << 8) | (k & 240) | (k >> 8);
}
// mixed-radix (8,16,16) un-reversal for the 2048 FFT
static __device__ __forceinline__ int unrev2048(int l) {
    return ((l & 7) << 8) | (((l >> 3) & 15) << 4) | ((l >> 7) & 15);
}

// output slot permutation of bfly16: X[q] lives in v[PERM16(q)] (involution)
#define PERM16(q) ((((q) & 3) << 2) | ((q) >> 2))

// ---------------------------------------------------------------------------
template<bool INV>
static __device__ __forceinline__ void dft4(float2& a, float2& b, float2& c, float2& d)
{
    float2 t0 = cadd(a, c), t1 = csub(a, c), t2 = cadd(b, d), t3 = csub(b, d);
    float2 j3 = INV ? make_float2(-t3.y, t3.x) : make_float2(t3.y, -t3.x);
    a = cadd(t0, t2); c = csub(t0, t2);
    b = cadd(t1, j3); d = csub(t1, j3);
}

template<bool INV>
static __device__ __forceinline__ float2 cmulw(float2 x, float wr, float wi)
{
    return cmul(x, make_float2(wr, INV ? -wi : wi));
}

template<bool INV>
static __device__ __forceinline__ void bfly16(float2 v[16])
{
    const float C1 = 0.9238795325112867f, S1 = 0.3826834323650898f, R2 = 0.7071067811865476f;
    dft4<INV>(v[0], v[4], v[8],  v[12]);
    dft4<INV>(v[1], v[5], v[9],  v[13]);
    dft4<INV>(v[2], v[6], v[10], v[14]);
    dft4<INV>(v[3], v[7], v[11], v[15]);
    v[5]  = cmulw<INV>(v[5],  C1, -S1);
    v[6]  = cmulw<INV>(v[6],  R2, -R2);
    v[7]  = cmulw<INV>(v[7],  S1, -C1);
    v[9]  = cmulw<INV>(v[9],  R2, -R2);
    v[10] = cmulw<INV>(v[10], 0.f, -1.f);
    v[11] = cmulw<INV>(v[11], -R2, -R2);
    v[13] = cmulw<INV>(v[13], S1, -C1);
    v[14] = cmulw<INV>(v[14], -R2, -R2);
    v[15] = cmulw<INV>(v[15], -C1,  S1);
    dft4<INV>(v[0],  v[1],  v[2],  v[3]);
    dft4<INV>(v[4],  v[5],  v[6],  v[7]);
    dft4<INV>(v[8],  v[9],  v[10], v[11]);
    dft4<INV>(v[12], v[13], v[14], v[15]);
}

template<bool FREQ>
static __device__ __forceinline__ void twapply16(float2 v[16], float2 w1)
{
#define TSLOT(q) (FREQ ? (q) : PERM16(q))
    float2 w2 = cmul(w1, w1);
    v[TSLOT(1)] = cmul(v[TSLOT(1)], w1);
    v[TSLOT(2)] = cmul(v[TSLOT(2)], w2);
    float2 w3 = cmul(w2, w1);
    v[TSLOT(3)] = cmul(v[TSLOT(3)], w3);
    float2 w4 = cmul(w2, w2);
    v[TSLOT(4)] = cmul(v[TSLOT(4)], w4);
    float2 w5 = cmul(w4, w1);
    v[TSLOT(5)] = cmul(v[TSLOT(5)], w5);
    float2 w6 = cmul(w4, w2);
    v[TSLOT(6)] = cmul(v[TSLOT(6)], w6);
    float2 w7 = cmul(w4, w3);
    v[TSLOT(7)] = cmul(v[TSLOT(7)], w7);
    float2 w8 = cmul(w4, w4);
    v[TSLOT(8)]  = cmul(v[TSLOT(8)],  w8);
    v[TSLOT(9)]  = cmul(v[TSLOT(9)],  cmul(w8, w1));
    v[TSLOT(10)] = cmul(v[TSLOT(10)], cmul(w8, w2));
    v[TSLOT(11)] = cmul(v[TSLOT(11)], cmul(w8, w3));
    v[TSLOT(12)] = cmul(v[TSLOT(12)], cmul(w8, w4));
    v[TSLOT(13)] = cmul(v[TSLOT(13)], cmul(w8, w5));
    v[TSLOT(14)] = cmul(v[TSLOT(14)], cmul(w8, w6));
    v[TSLOT(15)] = cmul(v[TSLOT(15)], cmul(w8, w7));
#undef TSLOT
}

template<bool INV>
static __device__ void stage16(float2* buf, const float2* __restrict__ tw,
                               int L, int NB, int gtid, int GT)
{
    const int m = L >> 4;
    const int twstep = L2X / L;
    for (int b = gtid; b < NB; b += GT) {
        int j = b & (m - 1);
        int base = ((b - j) << 4) + j;
        float2 v[16];
        #pragma unroll
        for (int r = 0; r < 16; r++) v[r] = buf[PIDX(base + m * r)];

        if (!INV) {
            bfly16<false>(v);
            if (m > 1) {
                float2 w1 = tw[j * twstep];
                twapply16<false>(v, w1);
            }
        } else {
            if (m > 1) {
                float2 w1 = tw[j * twstep]; w1.y = -w1.y;
                twapply16<true>(v, w1);
            }
            bfly16<true>(v);
        }
        #pragma unroll
        for (int q = 0; q < 16; q++) buf[PIDX(base + m * q)] = v[PERM16(q)];
    }
}

template<bool INV>
static __device__ __forceinline__ void bfly8(float2 v[8])
{
    const float t = 0.70710678118654752f;
    float2 a0 = cadd(v[0], v[4]), a4 = csub(v[0], v[4]);
    float2 a1 = cadd(v[1], v[5]), a5 = csub(v[1], v[5]);
    float2 a2 = cadd(v[2], v[6]), a6 = csub(v[2], v[6]);
    float2 a3 = cadd(v[3], v[7]), a7 = csub(v[3], v[7]);
    float2 b0 = cadd(a0, a2), b2 = csub(a0, a2);
    float2 b1 = cadd(a1, a3), b3 = csub(a1, a3);
    float2 m4b3 = INV ? make_float2(-b3.y, b3.x) : make_float2(b3.y, -b3.x);
    v[0] = cadd(b0, b1);  v[4] = csub(b0, b1);
    v[2] = cadd(b2, m4b3); v[6] = csub(b2, m4b3);
    float2 c0 = a4;
    float2 c1 = INV ? make_float2(t * (a5.x - a5.y), t * (a5.x + a5.y))
                    : make_float2(t * (a5.x + a5.y), t * (a5.y - a5.x));
    float2 c2 = INV ? make_float2(-a6.y, a6.x) : make_float2(a6.y, -a6.x);
    float2 c3 = INV ? make_float2(-t * (a7.x + a7.y), t * (a7.x - a7.y))
                    : make_float2(t * (a7.y - a7.x), -t * (a7.x + a7.y));
    float2 d0 = cadd(c0, c2), d2 = csub(c0, c2);
    float2 d1 = cadd(c1, c3), d3 = csub(c1, c3);
    float2 m4d3 = INV ? make_float2(-d3.y, d3.x) : make_float2(d3.y, -d3.x);
    v[1] = cadd(d0, d1);  v[5] = csub(d0, d1);
    v[3] = cadd(d2, m4d3); v[7] = csub(d2, m4d3);
}

template<bool INV>
static __device__ void stage8(float2* buf, const float2* __restrict__ tw,
                              int L, int NB, int gtid, int GT)
{
    int m = L >> 3;
    int twstep = L2X / L;
    for (int b = gtid; b < NB; b += GT) {
        int j = b & (m - 1);
        int base = ((b - j) << 3) + j;
        float2 v[8];
        #pragma unroll
        for (int r = 0; r < 8; r++) v[r] = buf[PIDX(base + m * r)];

        if (m > 1) {
            float2 w = tw[j * twstep];
            if (INV) w.y = -w.y;
            if (!INV) {
                bfly8<false>(v);
                float2 wq = w;
                v[1] = cmul(v[1], wq);
                #pragma unroll
                for (int q = 2; q < 8; q++) { wq = cmul(wq, w); v[q] = cmul(v[q], wq); }
            } else {
                float2 wq = w;
                v[1] = cmul(v[1], wq);
                #pragma unroll
                for (int q = 2; q < 8; q++) { wq = cmul(wq, w); v[q] = cmul(v[q], wq); }
                bfly8<true>(v);
            }
        } else {
            bfly8<INV>(v);
        }
        #pragma unroll
        for (int r = 0; r < 8; r++) buf[PIDX(base + m * r)] = v[r];
    }
}

// ---------------------------------------------------------------------------
// Stage A: at_roots via Woodbury + half-angle identity (unchanged from R13).
// ---------------------------------------------------------------------------
__global__ __launch_bounds__(256, 4)
void at_roots_kernel(const float* __restrict__ p_ri,
                     const float* __restrict__ lambda_ri,
                     const float* __restrict__ B_ri,
                     const float* __restrict__ Ct_ri,
                     const float* __restrict__ log_step)
{
    __shared__ ulonglong2 s_nl[N_STATE];
    __shared__ ull        s_lx2[N_STATE];
    __shared__ ulonglong2 s_cb[N_STATE];
    __shared__ ulonglong2 s_cp[N_STATE];
    __shared__ ulonglong2 s_pb[N_STATE];
    __shared__ ull        s_pp[N_STATE];

    int d = blockIdx.x;
    int jlo = blockIdx.y * 512;
    int tid = threadIdx.x;

    if (tid < N_STATE) {
        int n = tid;
        float pr = p_ri[2 * n], pi = p_ri[2 * n + 1];
        float2 lam = make_float2(lambda_ri[2 * n], lambda_ri[2 * n + 1]);
        float2 Bv  = make_float2(B_ri[(d * N_STATE + n) * 2], B_ri[(d * N_STATE + n) * 2 + 1]);
        float2 Ctc = make_float2(Ct_ri[(d * N_STATE + n) * 2], -Ct_ri[(d * N_STATE + n) * 2 + 1]);
        float2 CtB = cmul(Ctc, Bv);
        float2 Ctp = cmul(Ctc, make_float2(pr, pi));
        float2 pB  = cmul(make_float2(pr, -pi), Bv);
        float  pp  = pr * pr + pi * pi;
        ull a, b;
        F2PACK(a, -lam.x, -lam.x); F2PACK(b, -lam.y, -lam.y); s_nl[n] = make_ulonglong2(a, b);
        F2PACK(a, lam.x * lam.x, lam.x * lam.x); s_lx2[n] = a;
        F2PACK(a, CtB.x, CtB.x);   F2PACK(b, CtB.y, CtB.y);   s_cb[n] = make_ulonglong2(a, b);
        F2PACK(a, Ctp.x, Ctp.x);   F2PACK(b, Ctp.y, Ctp.y);   s_cp[n] = make_ulonglong2(a, b);
        F2PACK(a, pB.x,  pB.x);    F2PACK(b, pB.y,  pB.y);    s_pb[n] = make_ulonglong2(a, b);
        F2PACK(a, pp, pp);         s_pp[n] = a;
    }
    __syncthreads();

    float tos = 2.0f * __expf(-log_step[d]);

    int j0 = jlo + 2 * tid;

    float tj[2], gyv[2];
    #pragma unroll
    for (int e = 0; e < 2; e++) {
        int j = j0 + e;
        float h = (float)j * (3.14159265358979323846f / 2048.0f);
        float t = tanf(h);
        tj[e]  = t;
        gyv[e] = -tos * t;
    }
    ull gy2;
    F2PACK(gy2, gyv[0], gyv[1]);

    ull k00x = 0, k00y = 0, k00s = 0;
    ull k01x = 0, k01y = 0, k01s = 0;
    ull k10x = 0, k10y = 0, k10s = 0;
    ull k11x = 0, k11s = 0;

    #pragma unroll 8
    for (int n = 0; n < N_STATE; n++) {
        ulonglong2 nl = s_nl[n];
        ull lx2 = s_lx2[n];
        ulonglong2 cb = s_cb[n];
        ulonglong2 cp = s_cp[n];
        ulonglong2 pb = s_pb[n];
        ull ppv = s_pp[n];
        ull dcy, m2, r, ix, t;
        F2ADD(dcy, gy2, nl.y);
        F2FMA(m2, dcy, dcy, lx2);
        float mlo, mhi, rlo, rhi;
        F2UNPK(mlo, mhi, m2);
        FRCP(rlo, mlo);
        FRCP(rhi, mhi);
        F2PACK(r, rlo, rhi);
        F2MUL(ix, nl.x, r);
        F2MUL(t,  dcy, r);
        F2FMA(k00x, cb.x, ix, k00x);
        F2FMA(k00x, cb.y, t,  k00x);
        F2FMA(k00y, cb.y, ix, k00y);
        F2FMA(k00s, cb.x, t,  k00s);
        F2FMA(k01x, cp.x, ix, k01x);
        F2FMA(k01x, cp.y, t,  k01x);
        F2FMA(k01y, cp.y, ix, k01y);
        F2FMA(k01s, cp.x, t,  k01s);
        F2FMA(k10x, pb.x, ix, k10x);
        F2FMA(k10x, pb.y, t,  k10x);
        F2FMA(k10y, pb.y, ix, k10y);
        F2FMA(k10s, pb.x, t,  k10s);
        F2FMA(k11x, ppv, ix, k11x);
        F2FMA(k11s, ppv, t,  k11s);
    }

    float a00x[2], a00y[2], a01x[2], a01y[2], a10x[2], a10y[2], a11x[2], a11y[2];
    F2UNPK(a00x[0], a00x[1], k00x);
    { float y0,y1,s0,s1; F2UNPK(y0,y1,k00y); F2UNPK(s0,s1,k00s); a00y[0]=y0-s0; a00y[1]=y1-s1; }
    F2UNPK(a01x[0], a01x[1], k01x);
    { float y0,y1,s0,s1; F2UNPK(y0,y1,k01y); F2UNPK(s0,s1,k01s); a01y[0]=y0-s0; a01y[1]=y1-s1; }
    F2UNPK(a10x[0], a10x[1], k10x);
    { float y0,y1,s0,s1; F2UNPK(y0,y1,k10y); F2UNPK(s0,s1,k10s); a10y[0]=y0-s0; a10y[1]=y1-s1; }
    F2UNPK(a11x[0], a11x[1], k11x);
    { float s0,s1; F2UNPK(s0,s1,k11s); a11y[0]=-s0; a11y[1]=-s1; }

    float4 outv;
    #pragma unroll
    for (int e = 0; e < 2; e++) {
        float2 k00 = make_float2(a00x[e], a00y[e]);
        float2 k01 = make_float2(a01x[e], a01y[e]);
        float2 k10 = make_float2(a10x[e], a10y[e]);
        float2 den = make_float2(1.0f + a11x[e], a11y[e]);
        float rd = __fdividef(1.0f, den.x * den.x + den.y * den.y);
        float2 iden = make_float2(den.x * rd, -den.y * rd);
        float2 frac = cmul(cmul(k01, k10), iden);
        float2 z = csub(k00, frac);
        float2 res = make_float2(z.x + tj[e] * z.y, z.y - tj[e] * z.x);
        if (e == 0) { outv.x = res.x; outv.y = res.y; }
        else        { outv.z = res.x; outv.w = res.y; }
    }
    *(float4*)&g_at[d * LSEQ + j0] = outv;
}

// ---------------------------------------------------------------------------
// Stage B (split-bin, POSITION-ORDERED output):
//   even k=2m: Kf = Dp + (at[(2048-m)%2048] + conj(at[m]))/2  (staged in bufA[m])
//   odd  k=2m+1: twisted 2048-FFT result in bufB (digit-reversed-2048)
//   g_kf[d][p] = Kf[rev16(p)] / 4096  (matches conv's smem position layout)
// ---------------------------------------------------------------------------
__global__ void kf_kernel(const float* __restrict__ Dp)
{
    extern __shared__ float2 sm[];
    float2* tw   = sm;                 // 512 (W_4096^k, k<512)
    float2* bufA = sm + 512;           // padded 2048
    float2* bufB = sm + 512 + 2184;    // padded 2048

    int d = blockIdx.x;
    int tid = threadIdx.x;
    const int T = 256;

    for (int k = tid; k < 512; k += T) {
        float s, c;
        sincosf(6.283185307179586f * (float)k * (1.0f / 4096.0f), &s, &c);
        tw[k] = make_float2(c, -s);
    }
    for (int j = tid; j < LSEQ; j += T) bufA[PIDX(j)] = g_at[d * LSEQ + j];
    __syncthreads();

    // ---- FFT-2048 of at: radices 8,16,16 -> B (digit-reversed) ----
    stage8 <false>(bufA, tw, 2048, 256, tid, T); __syncthreads();
    stage16<false>(bufA, tw,  256, 128, tid, T); __syncthreads();
    stage16<false>(bufA, tw,   16, 128, tid, T); __syncthreads();

    // ---- twist: bufB[l] = (Re(B[l])/2048 + dp*delta0) * W_4096^l ----
    float dp = Dp[d];
    const float R2 = 0.7071067811865476f;
    #pragma unroll
    for (int t = 0; t < 4; t++) {
        float w8x = (t == 0) ? 1.0f : (t == 1) ? R2 : (t == 2) ? 0.0f : -R2;
        float w8y = (t == 0) ? 0.0f : (t == 2) ? -1.0f : -R2;
        for (int l2 = tid; l2 < 512; l2 += T) {
            int l = t * 512 + l2;
            int p = unrev2048(l);
            float kr = bufA[PIDX(p)].x * (1.0f / (float)LSEQ);
            if (l == 0) kr += dp;
            float2 w = cmul(tw[l2], make_float2(w8x, w8y));
            bufB[PIDX(l)] = make_float2(kr * w.x, kr * w.y);
        }
    }
    __syncthreads();

    // ---- FFT-2048 of twisted K' -> odd bins (digit-reversed) ----
    stage8 <false>(bufB, tw, 2048, 256, tid, T); __syncthreads();
    stage16<false>(bufB, tw,  256, 128, tid, T); __syncthreads();
    stage16<false>(bufB, tw,   16, 128, tid, T); __syncthreads();

    // ---- evens (closed form) staged into bufA[m], coalesced g_at reads ----
    for (int m = tid; m < LSEQ; m += T) {
        float2 a1 = g_at[d * LSEQ + ((LSEQ - m) & (LSEQ - 1))];
        float2 a2 = g_at[d * LSEQ + m];
        bufA[PIDX(m)] = make_float2(dp + 0.5f * (a1.x + a2.x), 0.5f * (a1.y - a2.y));
    }
    __syncthreads();

    // ---- position-ordered coalesced write; k parity uniform per iteration ----
    const float invN = 1.0f / (float)L2X;
    for (int p = tid; p < L2X; p += T) {
        int k = rev16(p);
        float2 v;
        if ((k & 1) == 0) v = bufA[PIDX(k >> 1)];
        else              v = bufB[PIDX(unrev2048(k >> 1))];
        g_kf[(size_t)d * L2X + p] = make_float2(v.x * invN, v.y * invN);
    }
}

// ---------------------------------------------------------------------------
// Stage C: causal FFT conv. The last forward stage (L=16), the Hermitian
// pointwise, and the first inverse stage (L=16) are FUSED in registers per
// thread over paired position-groups:
//   position p = 256c+16b+a holds bin k = rev16(p) = 256a+16b+c
//   pair k <-> 4096-k: group G=16c+b pairs with 271-G (slot a <-> 15-a) for
//   G>=16; groups 0..15 pair as (g, 16-g); groups 0 and 8 self-pair.
// Saves 4 smem sweeps (16 -> 12) and 3 barriers.
// ---------------------------------------------------------------------------
__global__ __launch_bounds__(256, 3)
void conv_kernel(const float* __restrict__ u,
                 float* __restrict__ y)
{
    extern __shared__ float2 sm[];
    float2* tw   = sm;                        // 256 (W_4096^k, k<256)
    float2* buf0 = sm + 256;
    float2* buf1 = sm + 256 + 4368;

    int tid = threadIdx.x;
    int q   = tid >> 7;
    int gt  = tid & 127;
    float2* buf = q ? buf1 : buf0;

    int b  = blockIdx.x >> 6;
    int cb = (blockIdx.x & 63) * 4;
    int c0 = cb + 2 * q;
    int barId = 1 + q;

    if (tid < 256) {
        float s, c;
        sincosf(6.283185307179586f * (float)tid * (1.0f / 4096.0f), &s, &c);
        tw[tid] = make_float2(c, -s);
    }

    const float4* ub4 = (const float4*)(u + (size_t)b * LSEQ * D_MODEL + cb);
    float4*       yb4 = (float4*)(y + (size_t)b * LSEQ * D_MODEL + cb);

    for (int l = tid; l < LSEQ; l += 256) {
        float4 f = ub4[(size_t)l * (D_MODEL / 4)];
        buf0[PIDX(l)] = make_float2(f.x, f.y);
        buf1[PIDX(l)] = make_float2(f.z, f.w);
    }
    for (int l = LSEQ + tid; l < L2X; l += 256) {
        buf0[PIDX(l)] = make_float2(0.0f, 0.0f);
        buf1[PIDX(l)] = make_float2(0.0f, 0.0f);
    }
    __syncthreads();

    stage16<false>(buf, tw, 4096, 256, gt, 128); barsync(barId, 128);
    stage16<false>(buf, tw,  256, 256, gt, 128); barsync(barId, 128);

    // ---- FUSED: fwd L=16 bfly + Hermitian pointwise + inv L=16 bfly ----
    {
        const float2* H0 = g_kf + (size_t)c0 * L2X;        // position-ordered
        const float2* H1 = g_kf + (size_t)(c0 + 1) * L2X;
        int G, Gh;
        if (gt < 120)      { G = 16 + gt;  Gh = 255 - gt; }
        else if (gt < 127) { int g = gt - 119; G = g; Gh = 16 - g; }
        else               { G = 0; Gh = 8; }

        float2 P[16], Q[16];
        #pragma unroll
        for (int r = 0; r < 16; r++) P[r] = buf[PIDX(16 * G + r)];
        #pragma unroll
        for (int r = 0; r < 16; r++) Q[r] = buf[PIDX(16 * Gh + r)];
        bfly16<false>(P);
        bfly16<false>(Q);
        // reorder to position-slot order: pos[s] = v[PERM16(s)]
        float2 Ps[16], Qs[16];
        #pragma unroll
        for (int s = 0; s < 16; s++) { Ps[s] = P[PERM16(s)]; Qs[s] = Q[PERM16(s)]; }

        if (gt < 127) {
            // generic: slot a of G (bin k) pairs with slot 15-a of Gh (bin 4096-k)
            #pragma unroll
            for (int a = 0; a < 16; a++) {
                float2 Zk = Ps[a], Zm = Qs[15 - a];
                float2 U0 = make_float2(0.5f * (Zk.x + Zm.x), 0.5f * (Zk.y - Zm.y));
                float2 U1 = make_float2(0.5f * (Zk.y + Zm.y), 0.5f * (Zm.x - Zk.x));
                float2 Y0 = cmul(U0, H0[16 * G + a]);
                float2 Y1 = cmul(U1, H1[16 * G + a]);
                Ps[a]      = make_float2(Y0.x - Y1.y, Y0.y + Y1.x);
                Qs[15 - a] = make_float2(Y0.x + Y1.y, Y1.x - Y0.y);
            }
        } else {
            // special: P = group 0 (slot a <-> slot (16-a)&15; a=0,8 self),
            //          Q = group 8 (slot a <-> slot 15-a)
            #pragma unroll
            for (int a = 0; a <= 8; a++) {
                int am = (16 - a) & 15;
                float2 Zk = Ps[a], Zm = Ps[am];
                float2 U0 = make_float2(0.5f * (Zk.x + Zm.x), 0.5f * (Zk.y - Zm.y));
                float2 U1 = make_float2(0.5f * (Zk.y + Zm.y), 0.5f * (Zm.x - Zk.x));
                float2 Y0 = cmul(U0, H0[a]);
                float2 Y1 = cmul(U1, H1[a]);
                Ps[a] = make_float2(Y0.x - Y1.y, Y0.y + Y1.x);
                if (a != 0 && a != 8)
                    Ps[am] = make_float2(Y0.x + Y1.y, Y1.x - Y0.y);
            }
            #pragma unroll
            for (int a = 0; a < 8; a++) {
                float2 Zk = Qs[a], Zm = Qs[15 - a];
                float2 U0 = make_float2(0.5f * (Zk.x + Zm.x), 0.5f * (Zk.y - Zm.y));
                float2 U1 = make_float2(0.5f * (Zk.y + Zm.y), 0.5f * (Zm.x - Zk.x));
                float2 Y0 = cmul(U0, H0[128 + a]);
                float2 Y1 = cmul(U1, H1[128 + a]);
                Qs[a]      = make_float2(Y0.x - Y1.y, Y0.y + Y1.x);
                Qs[15 - a] = make_float2(Y0.x + Y1.y, Y1.x - Y0.y);
            }
        }

        // inverse L=16 stage: input v[r] = pos[r], output to position 16G+q'
        bfly16<true>(Ps);
        bfly16<true>(Qs);
        #pragma unroll
        for (int s = 0; s < 16; s++) buf[PIDX(16 * G + s)] = Ps[PERM16(s)];
        #pragma unroll
        for (int s = 0; s < 16; s++) buf[PIDX(16 * Gh + s)] = Qs[PERM16(s)];
    }
    barsync(barId, 128);

    stage16<true>(buf, tw,  256, 256, gt, 128); barsync(barId, 128);
    stage16<true>(buf, tw, 4096, 256, gt, 128);
    __syncthreads();

    for (int l = tid; l < LSEQ; l += 256) {
        float2 r0 = buf0[PIDX(l)];
        float2 r1 = buf1[PIDX(l)];
        yb4[(size_t)l * (D_MODEL / 4)] = make_float4(r0.x, r0.y, r1.x, r1.y);
    }
}

// ---------------------------------------------------------------------------
extern "C" void kernel_launch(void* const* d_in, const int* in_sizes, int n_in,
                              void* d_out, int out_size)
{
    const float* u         = (const float*)d_in[0];
    const float* p_ri      = (const float*)d_in[1];
    const float* lambda_ri = (const float*)d_in[2];
    const float* B_ri      = (const float*)d_in[3];
    const float* Ct_ri     = (const float*)d_in[4];
    const float* Dp        = (const float*)d_in[5];
    const float* log_step  = (const float*)d_in[6];
    float* y = (float*)d_out;

    (void)in_sizes; (void)n_in; (void)out_size;

    const int KF_SMEM   = (512 + 2184 + 2184) * sizeof(float2);   // 39040
    const int CONV_SMEM = (256 + 2 * 4368) * sizeof(float2);      // 71936

    cudaFuncSetAttribute(kf_kernel,   cudaFuncAttributeMaxDynamicSharedMemorySize, KF_SMEM);
    cudaFuncSetAttribute(conv_kernel, cudaFuncAttributeMaxDynamicSharedMemorySize, CONV_SMEM);

    at_roots_kernel<<<dim3(D_MODEL, 4), 256>>>(p_ri, lambda_ri, B_ri, Ct_ri, log_step);
    kf_kernel<<<D_MODEL, 256, KF_SMEM>>>(Dp);
    conv_kernel<<<NBATCH * 64, 256, CONV_SMEM>>>(u, y);
}

// round 16
// speedup vs baseline: 1.2994x; 1.2994x over previous
#include <cuda_runtime.h>
#include <math.h>

#define D_MODEL 256
#define N_STATE 64
#define LSEQ    2048
#define L2X     4096
#define NBATCH  16

typedef unsigned long long ull;

// Scratch (no cudaMalloc allowed).
__device__ float2 g_at[D_MODEL * LSEQ];   // 4 MB
__device__ float2 g_kf[D_MODEL * L2X];    // 8 MB, NATURAL freq order, pre-scaled by 1/4096

static __device__ __forceinline__ float2 cmul(float2 a, float2 b) {
    return make_float2(a.x * b.x - a.y * b.y, a.x * b.y + a.y * b.x);
}
static __device__ __forceinline__ float2 cadd(float2 a, float2 b) {
    return make_float2(a.x + b.x, a.y + b.y);
}
static __device__ __forceinline__ float2 csub(float2 a, float2 b) {
    return make_float2(a.x - b.x, a.y - b.y);
}

static __device__ __forceinline__ void barsync(int id, int nthr) {
    asm volatile("bar.sync %0, %1;" :: "r"(id), "r"(nthr) : "memory");
}

// packed f32x2 ops (sm_103a; FFMA2 only reachable via PTX)
#define F2ADD(d,a,b)   asm("add.rn.f32x2 %0,%1,%2;"    : "=l"(d) : "l"(a), "l"(b))
#define F2MUL(d,a,b)   asm("mul.rn.f32x2 %0,%1,%2;"    : "=l"(d) : "l"(a), "l"(b))
#define F2FMA(d,a,b,c) asm("fma.rn.f32x2 %0,%1,%2,%3;" : "=l"(d) : "l"(a), "l"(b), "l"(c))
#define F2PACK(d,lo,hi) asm("mov.b64 %0,{%1,%2};" : "=l"(d) : "f"(lo), "f"(hi))
#define F2UNPK(lo,hi,v) asm("mov.b64 {%0,%1},%2;" : "=f"(lo), "=f"(hi) : "l"(v))
#define FRCP(d,a)      asm("rcp.approx.f32 %0,%1;" : "=f"(d) : "f"(a))

// Triple-pad smem addressing: conflict-free for strides 256, 16, 1.
#define PIDX(a) ((a) + ((a) >> 4) + ((a) >> 8))

// radix-16 digit reversal for N=4096 (digits 16,16,16)
static __device__ __forceinline__ int rev16(int k) {
    return ((k & 15) << 8) | (k & 240) | (k >> 8);
}
// mixed-radix (8,16,16) un-reversal for the 2048 FFT: natural l -> position
static __device__ __forceinline__ int unrev2048(int l) {
    return ((l & 7) << 8) | (((l >> 3) & 15) << 4) | ((l >> 7) & 15);
}

// output slot permutation of bfly16: X[q] lives in v[PERM16(q)]
#define PERM16(q) ((((q) & 3) << 2) | ((q) >> 2))

// ---------------------------------------------------------------------------
template<bool INV>
static __device__ __forceinline__ void dft4(float2& a, float2& b, float2& c, float2& d)
{
    float2 t0 = cadd(a, c), t1 = csub(a, c), t2 = cadd(b, d), t3 = csub(b, d);
    float2 j3 = INV ? make_float2(-t3.y, t3.x) : make_float2(t3.y, -t3.x);
    a = cadd(t0, t2); c = csub(t0, t2);
    b = cadd(t1, j3); d = csub(t1, j3);
}

template<bool INV>
static __device__ __forceinline__ float2 cmulw(float2 x, float wr, float wi)
{
    return cmul(x, make_float2(wr, INV ? -wi : wi));
}

template<bool INV>
static __device__ __forceinline__ void bfly16(float2 v[16])
{
    const float C1 = 0.9238795325112867f, S1 = 0.3826834323650898f, R2 = 0.7071067811865476f;
    dft4<INV>(v[0], v[4], v[8],  v[12]);
    dft4<INV>(v[1], v[5], v[9],  v[13]);
    dft4<INV>(v[2], v[6], v[10], v[14]);
    dft4<INV>(v[3], v[7], v[11], v[15]);
    v[5]  = cmulw<INV>(v[5],  C1, -S1);
    v[6]  = cmulw<INV>(v[6],  R2, -R2);
    v[7]  = cmulw<INV>(v[7],  S1, -C1);
    v[9]  = cmulw<INV>(v[9],  R2, -R2);
    v[10] = cmulw<INV>(v[10], 0.f, -1.f);
    v[11] = cmulw<INV>(v[11], -R2, -R2);
    v[13] = cmulw<INV>(v[13], S1, -C1);
    v[14] = cmulw<INV>(v[14], -R2, -R2);
    v[15] = cmulw<INV>(v[15], -C1,  S1);
    dft4<INV>(v[0],  v[1],  v[2],  v[3]);
    dft4<INV>(v[4],  v[5],  v[6],  v[7]);
    dft4<INV>(v[8],  v[9],  v[10], v[11]);
    dft4<INV>(v[12], v[13], v[14], v[15]);
}

template<bool FREQ>
static __device__ __forceinline__ void twapply16(float2 v[16], float2 w1)
{
#define TSLOT(q) (FREQ ? (q) : PERM16(q))
    float2 w2 = cmul(w1, w1);
    v[TSLOT(1)] = cmul(v[TSLOT(1)], w1);
    v[TSLOT(2)] = cmul(v[TSLOT(2)], w2);
    float2 w3 = cmul(w2, w1);
    v[TSLOT(3)] = cmul(v[TSLOT(3)], w3);
    float2 w4 = cmul(w2, w2);
    v[TSLOT(4)] = cmul(v[TSLOT(4)], w4);
    float2 w5 = cmul(w4, w1);
    v[TSLOT(5)] = cmul(v[TSLOT(5)], w5);
    float2 w6 = cmul(w4, w2);
    v[TSLOT(6)] = cmul(v[TSLOT(6)], w6);
    float2 w7 = cmul(w4, w3);
    v[TSLOT(7)] = cmul(v[TSLOT(7)], w7);
    float2 w8 = cmul(w4, w4);
    v[TSLOT(8)]  = cmul(v[TSLOT(8)],  w8);
    v[TSLOT(9)]  = cmul(v[TSLOT(9)],  cmul(w8, w1));
    v[TSLOT(10)] = cmul(v[TSLOT(10)], cmul(w8, w2));
    v[TSLOT(11)] = cmul(v[TSLOT(11)], cmul(w8, w3));
    v[TSLOT(12)] = cmul(v[TSLOT(12)], cmul(w8, w4));
    v[TSLOT(13)] = cmul(v[TSLOT(13)], cmul(w8, w5));
    v[TSLOT(14)] = cmul(v[TSLOT(14)], cmul(w8, w6));
    v[TSLOT(15)] = cmul(v[TSLOT(15)], cmul(w8, w7));
#undef TSLOT
}

template<bool INV>
static __device__ void stage16(float2* buf, const float2* __restrict__ tw,
                               int L, int NB, int gtid, int GT)
{
    const int m = L >> 4;
    const int twstep = L2X / L;
    for (int b = gtid; b < NB; b += GT) {
        int j = b & (m - 1);
        int base = ((b - j) << 4) + j;
        float2 v[16];
        #pragma unroll
        for (int r = 0; r < 16; r++) v[r] = buf[PIDX(base + m * r)];

        if (!INV) {
            bfly16<false>(v);
            if (m > 1) {
                float2 w1 = tw[j * twstep];
                twapply16<false>(v, w1);
            }
        } else {
            if (m > 1) {
                float2 w1 = tw[j * twstep]; w1.y = -w1.y;
                twapply16<true>(v, w1);
            }
            bfly16<true>(v);
        }
        #pragma unroll
        for (int q = 0; q < 16; q++) buf[PIDX(base + m * q)] = v[PERM16(q)];
    }
}

template<bool INV>
static __device__ __forceinline__ void bfly8(float2 v[8])
{
    const float t = 0.70710678118654752f;
    float2 a0 = cadd(v[0], v[4]), a4 = csub(v[0], v[4]);
    float2 a1 = cadd(v[1], v[5]), a5 = csub(v[1], v[5]);
    float2 a2 = cadd(v[2], v[6]), a6 = csub(v[2], v[6]);
    float2 a3 = cadd(v[3], v[7]), a7 = csub(v[3], v[7]);
    float2 b0 = cadd(a0, a2), b2 = csub(a0, a2);
    float2 b1 = cadd(a1, a3), b3 = csub(a1, a3);
    float2 m4b3 = INV ? make_float2(-b3.y, b3.x) : make_float2(b3.y, -b3.x);
    v[0] = cadd(b0, b1);  v[4] = csub(b0, b1);
    v[2] = cadd(b2, m4b3); v[6] = csub(b2, m4b3);
    float2 c0 = a4;
    float2 c1 = INV ? make_float2(t * (a5.x - a5.y), t * (a5.x + a5.y))
                    : make_float2(t * (a5.x + a5.y), t * (a5.y - a5.x));
    float2 c2 = INV ? make_float2(-a6.y, a6.x) : make_float2(a6.y, -a6.x);
    float2 c3 = INV ? make_float2(-t * (a7.x + a7.y), t * (a7.x - a7.y))
                    : make_float2(t * (a7.y - a7.x), -t * (a7.x + a7.y));
    float2 d0 = cadd(c0, c2), d2 = csub(c0, c2);
    float2 d1 = cadd(c1, c3), d3 = csub(c1, c3);
    float2 m4d3 = INV ? make_float2(-d3.y, d3.x) : make_float2(d3.y, -d3.x);
    v[1] = cadd(d0, d1);  v[5] = csub(d0, d1);
    v[3] = cadd(d2, m4d3); v[7] = csub(d2, m4d3);
}

template<bool INV>
static __device__ void stage8(float2* buf, const float2* __restrict__ tw,
                              int L, int NB, int gtid, int GT)
{
    int m = L >> 3;
    int twstep = L2X / L;
    for (int b = gtid; b < NB; b += GT) {
        int j = b & (m - 1);
        int base = ((b - j) << 3) + j;
        float2 v[8];
        #pragma unroll
        for (int r = 0; r < 8; r++) v[r] = buf[PIDX(base + m * r)];

        if (m > 1) {
            float2 w = tw[j * twstep];
            if (INV) w.y = -w.y;
            if (!INV) {
                bfly8<false>(v);
                float2 wq = w;
                v[1] = cmul(v[1], wq);
                #pragma unroll
                for (int q = 2; q < 8; q++) { wq = cmul(wq, w); v[q] = cmul(v[q], wq); }
            } else {
                float2 wq = w;
                v[1] = cmul(v[1], wq);
                #pragma unroll
                for (int q = 2; q < 8; q++) { wq = cmul(wq, w); v[q] = cmul(v[q], wq); }
                bfly8<true>(v);
            }
        } else {
            bfly8<INV>(v);
        }
        #pragma unroll
        for (int r = 0; r < 8; r++) buf[PIDX(base + m * r)] = v[r];
    }
}

// ---------------------------------------------------------------------------
// Stage A: at_roots via Woodbury + half-angle identity:
//   (1-w)/(1+w) = -i*tan(h),  2/(1+w) = 1 - i*tan(h),  h = pi*j/2048.
// g purely imaginary -> dc.x = -lam.x per-n constant. One tanf per j.
// f32x2-packed, 2 j per thread. grid (256,4).
// ---------------------------------------------------------------------------
__global__ __launch_bounds__(256, 4)
void at_roots_kernel(const float* __restrict__ p_ri,
                     const float* __restrict__ lambda_ri,
                     const float* __restrict__ B_ri,
                     const float* __restrict__ Ct_ri,
                     const float* __restrict__ log_step)
{
    __shared__ ulonglong2 s_nl[N_STATE];
    __shared__ ull        s_lx2[N_STATE];
    __shared__ ulonglong2 s_cb[N_STATE];
    __shared__ ulonglong2 s_cp[N_STATE];
    __shared__ ulonglong2 s_pb[N_STATE];
    __shared__ ull        s_pp[N_STATE];

    int d = blockIdx.x;
    int jlo = blockIdx.y * 512;
    int tid = threadIdx.x;

    if (tid < N_STATE) {
        int n = tid;
        float pr = p_ri[2 * n], pi = p_ri[2 * n + 1];
        float2 lam = make_float2(lambda_ri[2 * n], lambda_ri[2 * n + 1]);
        float2 Bv  = make_float2(B_ri[(d * N_STATE + n) * 2], B_ri[(d * N_STATE + n) * 2 + 1]);
        float2 Ctc = make_float2(Ct_ri[(d * N_STATE + n) * 2], -Ct_ri[(d * N_STATE + n) * 2 + 1]);
        float2 CtB = cmul(Ctc, Bv);
        float2 Ctp = cmul(Ctc, make_float2(pr, pi));
        float2 pB  = cmul(make_float2(pr, -pi), Bv);
        float  pp  = pr * pr + pi * pi;
        ull a, b;
        F2PACK(a, -lam.x, -lam.x); F2PACK(b, -lam.y, -lam.y); s_nl[n] = make_ulonglong2(a, b);
        F2PACK(a, lam.x * lam.x, lam.x * lam.x); s_lx2[n] = a;
        F2PACK(a, CtB.x, CtB.x);   F2PACK(b, CtB.y, CtB.y);   s_cb[n] = make_ulonglong2(a, b);
        F2PACK(a, Ctp.x, Ctp.x);   F2PACK(b, Ctp.y, Ctp.y);   s_cp[n] = make_ulonglong2(a, b);
        F2PACK(a, pB.x,  pB.x);    F2PACK(b, pB.y,  pB.y);    s_pb[n] = make_ulonglong2(a, b);
        F2PACK(a, pp, pp);         s_pp[n] = a;
    }
    __syncthreads();

    float tos = 2.0f * __expf(-log_step[d]);

    int j0 = jlo + 2 * tid;

    float tj[2], gyv[2];
    #pragma unroll
    for (int e = 0; e < 2; e++) {
        int j = j0 + e;
        float h = (float)j * (3.14159265358979323846f / 2048.0f);
        float t = tanf(h);                   // finite at j=1024 (fp32 pi/2)
        tj[e]  = t;
        gyv[e] = -tos * t;
    }
    ull gy2;
    F2PACK(gy2, gyv[0], gyv[1]);

    ull k00x = 0, k00y = 0, k00s = 0;
    ull k01x = 0, k01y = 0, k01s = 0;
    ull k10x = 0, k10y = 0, k10s = 0;
    ull k11x = 0, k11s = 0;

    #pragma unroll 8
    for (int n = 0; n < N_STATE; n++) {
        ulonglong2 nl = s_nl[n];
        ull lx2 = s_lx2[n];
        ulonglong2 cb = s_cb[n];
        ulonglong2 cp = s_cp[n];
        ulonglong2 pb = s_pb[n];
        ull ppv = s_pp[n];
        ull dcy, m2, r, ix, t;
        F2ADD(dcy, gy2, nl.y);
        F2FMA(m2, dcy, dcy, lx2);
        float mlo, mhi, rlo, rhi;
        F2UNPK(mlo, mhi, m2);
        FRCP(rlo, mlo);
        FRCP(rhi, mhi);
        F2PACK(r, rlo, rhi);
        F2MUL(ix, nl.x, r);
        F2MUL(t,  dcy, r);
        F2FMA(k00x, cb.x, ix, k00x);
        F2FMA(k00x, cb.y, t,  k00x);
        F2FMA(k00y, cb.y, ix, k00y);
        F2FMA(k00s, cb.x, t,  k00s);
        F2FMA(k01x, cp.x, ix, k01x);
        F2FMA(k01x, cp.y, t,  k01x);
        F2FMA(k01y, cp.y, ix, k01y);
        F2FMA(k01s, cp.x, t,  k01s);
        F2FMA(k10x, pb.x, ix, k10x);
        F2FMA(k10x, pb.y, t,  k10x);
        F2FMA(k10y, pb.y, ix, k10y);
        F2FMA(k10s, pb.x, t,  k10s);
        F2FMA(k11x, ppv, ix, k11x);
        F2FMA(k11s, ppv, t,  k11s);
    }

    float a00x[2], a00y[2], a01x[2], a01y[2], a10x[2], a10y[2], a11x[2], a11y[2];
    F2UNPK(a00x[0], a00x[1], k00x);
    { float y0,y1,s0,s1; F2UNPK(y0,y1,k00y); F2UNPK(s0,s1,k00s); a00y[0]=y0-s0; a00y[1]=y1-s1; }
    F2UNPK(a01x[0], a01x[1], k01x);
    { float y0,y1,s0,s1; F2UNPK(y0,y1,k01y); F2UNPK(s0,s1,k01s); a01y[0]=y0-s0; a01y[1]=y1-s1; }
    F2UNPK(a10x[0], a10x[1], k10x);
    { float y0,y1,s0,s1; F2UNPK(y0,y1,k10y); F2UNPK(s0,s1,k10s); a10y[0]=y0-s0; a10y[1]=y1-s1; }
    F2UNPK(a11x[0], a11x[1], k11x);
    { float s0,s1; F2UNPK(s0,s1,k11s); a11y[0]=-s0; a11y[1]=-s1; }

    float4 outv;
    #pragma unroll
    for (int e = 0; e < 2; e++) {
        float2 k00 = make_float2(a00x[e], a00y[e]);
        float2 k01 = make_float2(a01x[e], a01y[e]);
        float2 k10 = make_float2(a10x[e], a10y[e]);
        float2 den = make_float2(1.0f + a11x[e], a11y[e]);
        float rd = __fdividef(1.0f, den.x * den.x + den.y * den.y);
        float2 iden = make_float2(den.x * rd, -den.y * rd);
        float2 frac = cmul(cmul(k01, k10), iden);
        float2 z = csub(k00, frac);
        float2 res = make_float2(z.x + tj[e] * z.y, z.y - tj[e] * z.x);
        if (e == 0) { outv.x = res.x; outv.y = res.y; }
        else        { outv.z = res.x; outv.w = res.y; }
    }
    *(float4*)&g_at[d * LSEQ + j0] = outv;
}

// ---------------------------------------------------------------------------
// Stage B (split-bin form). Per channel d, with B = DFT_2048(at),
// K'[l] = Re(B[l])/2048 + Dp*delta0:
//   EVEN bins: Kf[2m] = Dp + (at[(2048-m)%2048] + conj(at[m]))/2   (closed form)
//   ODD bins:  Kf[2m+1] = DFT_2048(K'[l] * W_4096^l)[m]            (twisted FFT)
// Both pre-scaled by 1/4096. NATURAL-order g_kf.
// ---------------------------------------------------------------------------
__global__ void kf_kernel(const float* __restrict__ Dp)
{
    extern __shared__ float2 sm[];
    float2* tw   = sm;                 // 512 (W_4096^k, k<512)
    float2* bufA = sm + 512;           // padded 2048 -> 2184
    float2* bufB = sm + 512 + 2184;    // padded 2048 -> 2184

    int d = blockIdx.x;
    int tid = threadIdx.x;
    const int T = 256;

    for (int k = tid; k < 512; k += T) {
        float s, c;
        sincosf(6.283185307179586f * (float)k * (1.0f / 4096.0f), &s, &c);
        tw[k] = make_float2(c, -s);
    }
    for (int j = tid; j < LSEQ; j += T) bufA[PIDX(j)] = g_at[d * LSEQ + j];
    __syncthreads();

    // ---- FFT-2048 of at: radices 8,16,16 -> B (digit-reversed) ----
    stage8 <false>(bufA, tw, 2048, 256, tid, T); __syncthreads();
    stage16<false>(bufA, tw,  256, 128, tid, T); __syncthreads();
    stage16<false>(bufA, tw,   16, 128, tid, T); __syncthreads();

    // ---- twist: bufB[l] = (Re(B[l])/2048 + dp*delta0) * W_4096^l ----
    float dp = Dp[d];
    const float R2 = 0.7071067811865476f;
    #pragma unroll
    for (int t = 0; t < 4; t++) {
        float w8x = (t == 0) ? 1.0f : (t == 1) ? R2 : (t == 2) ? 0.0f : -R2;
        float w8y = (t == 0) ? 0.0f : (t == 2) ? -1.0f : -R2;
        for (int l2 = tid; l2 < 512; l2 += T) {
            int l = t * 512 + l2;
            int p = unrev2048(l);
            float kr = bufA[PIDX(p)].x * (1.0f / (float)LSEQ);
            if (l == 0) kr += dp;
            float2 w = cmul(tw[l2], make_float2(w8x, w8y));
            bufB[PIDX(l)] = make_float2(kr * w.x, kr * w.y);
        }
    }
    __syncthreads();

    // ---- FFT-2048 of twisted K' -> odd bins (digit-reversed) ----
    stage8 <false>(bufB, tw, 2048, 256, tid, T); __syncthreads();
    stage16<false>(bufB, tw,  256, 128, tid, T); __syncthreads();
    stage16<false>(bufB, tw,   16, 128, tid, T); __syncthreads();

    // ---- write even (closed form) + odd together as float4 ----
    const float invN = 1.0f / (float)L2X;
    for (int m = tid; m < LSEQ; m += T) {
        float2 a1 = g_at[d * LSEQ + ((LSEQ - m) & (LSEQ - 1))];
        float2 a2 = g_at[d * LSEQ + m];
        float ex = (dp + 0.5f * (a1.x + a2.x)) * invN;
        float ey = 0.5f * (a1.y - a2.y) * invN;
        float2 Dm = bufB[PIDX(unrev2048(m))];
        *(float4*)&g_kf[(size_t)d * L2X + 2 * m] =
            make_float4(ex, ey, Dm.x * invN, Dm.y * invN);
    }
}

// ---------------------------------------------------------------------------
// Stage C: causal FFT conv. 4 channels/block, 2 groups of 128 threads,
// block-wide float4 gmem, Dp & 1/4096 folded into Kf. No register-heavy
// fusions: >16 live float2/thread under the 3-CTA cap spills (R7, R14).
// ---------------------------------------------------------------------------
__global__ __launch_bounds__(256, 3)
void conv_kernel(const float* __restrict__ u,
                 float* __restrict__ y)
{
    extern __shared__ float2 sm[];
    float2* tw   = sm;                        // 256 (W_4096^k, k<256)
    float2* buf0 = sm + 256;
    float2* buf1 = sm + 256 + 4368;

    int tid = threadIdx.x;
    int q   = tid >> 7;
    int gt  = tid & 127;
    float2* buf = q ? buf1 : buf0;

    int b  = blockIdx.x >> 6;
    int cb = (blockIdx.x & 63) * 4;
    int c0 = cb + 2 * q;
    int barId = 1 + q;

    if (tid < 256) {
        float s, c;
        sincosf(6.283185307179586f * (float)tid * (1.0f / 4096.0f), &s, &c);
        tw[tid] = make_float2(c, -s);
    }

    const float4* ub4 = (const float4*)(u + (size_t)b * LSEQ * D_MODEL + cb);
    float4*       yb4 = (float4*)(y + (size_t)b * LSEQ * D_MODEL + cb);

    for (int l = tid; l < LSEQ; l += 256) {
        float4 f = ub4[(size_t)l * (D_MODEL / 4)];
        buf0[PIDX(l)] = make_float2(f.x, f.y);
        buf1[PIDX(l)] = make_float2(f.z, f.w);
    }
    for (int l = LSEQ + tid; l < L2X; l += 256) {
        buf0[PIDX(l)] = make_float2(0.0f, 0.0f);
        buf1[PIDX(l)] = make_float2(0.0f, 0.0f);
    }
    __syncthreads();

    stage16<false>(buf, tw, 4096, 256, gt, 128); barsync(barId, 128);
    stage16<false>(buf, tw,  256, 256, gt, 128); barsync(barId, 128);
    stage16<false>(buf, tw,   16, 256, gt, 128); barsync(barId, 128);

    for (int k = gt; k <= 2048; k += 128) {
        int mk = (L2X - k) & (L2X - 1);
        int pk = PIDX(rev16(k));
        int pm = PIDX(rev16(mk));
        float2 Zk = buf[pk], Zm = buf[pm];
        float2 U0 = make_float2(0.5f * (Zk.x + Zm.x), 0.5f * (Zk.y - Zm.y));
        float2 U1 = make_float2(0.5f * (Zk.y + Zm.y), 0.5f * (Zm.x - Zk.x));
        float2 H0 = g_kf[(size_t)c0 * L2X + k];
        float2 H1 = g_kf[(size_t)(c0 + 1) * L2X + k];
        float2 Y0 = cmul(U0, H0);
        float2 Y1 = cmul(U1, H1);
        buf[pk] = make_float2(Y0.x - Y1.y, Y0.y + Y1.x);
        if (k != 0 && k != 2048)
            buf[pm] = make_float2(Y0.x + Y1.y, Y1.x - Y0.y);
    }
    barsync(barId, 128);

    stage16<true>(buf, tw,   16, 256, gt, 128); barsync(barId, 128);
    stage16<true>(buf, tw,  256, 256, gt, 128); barsync(barId, 128);
    stage16<true>(buf, tw, 4096, 256, gt, 128);
    __syncthreads();

    for (int l = tid; l < LSEQ; l += 256) {
        float2 r0 = buf0[PIDX(l)];
        float2 r1 = buf1[PIDX(l)];
        yb4[(size_t)l * (D_MODEL / 4)] = make_float4(r0.x, r0.y, r1.x, r1.y);
    }
}

// ---------------------------------------------------------------------------
extern "C" void kernel_launch(void* const* d_in, const int* in_sizes, int n_in,
                              void* d_out, int out_size)
{
    const float* u         = (const float*)d_in[0];
    const float* p_ri      = (const float*)d_in[1];
    const float* lambda_ri = (const float*)d_in[2];
    const float* B_ri      = (const float*)d_in[3];
    const float* Ct_ri     = (const float*)d_in[4];
    const float* Dp        = (const float*)d_in[5];
    const float* log_step  = (const float*)d_in[6];
    float* y = (float*)d_out;

    (void)in_sizes; (void)n_in; (void)out_size;

    const int KF_SMEM   = (512 + 2184 + 2184) * sizeof(float2);   // 39040
    const int CONV_SMEM = (256 + 2 * 4368) * sizeof(float2);      // 71936

    cudaFuncSetAttribute(kf_kernel,   cudaFuncAttributeMaxDynamicSharedMemorySize, KF_SMEM);
    cudaFuncSetAttribute(conv_kernel, cudaFuncAttributeMaxDynamicSharedMemorySize, CONV_SMEM);

    at_roots_kernel<<<dim3(D_MODEL, 4), 256>>>(p_ri, lambda_ri, B_ri, Ct_ri, log_step);
    kf_kernel<<<D_MODEL, 256, KF_SMEM>>>(Dp);
    conv_kernel<<<NBATCH * 64, 256, CONV_SMEM>>>(u, y);
}

// round 17
// speedup vs baseline: 1.3749x; 1.0581x over previous
#include <cuda_runtime.h>
#include <math.h>

#define D_MODEL 256
#define N_STATE 64
#define LSEQ    2048
#define L2X     4096
#define NBATCH  16

typedef unsigned long long ull;

// Scratch (no cudaMalloc allowed).
__device__ float2 g_at[D_MODEL * LSEQ];   // 4 MB
__device__ float2 g_kf[D_MODEL * L2X];    // 8 MB, NATURAL freq order, pre-scaled by 1/4096

static __device__ __forceinline__ float2 cmul(float2 a, float2 b) {
    return make_float2(a.x * b.x - a.y * b.y, a.x * b.y + a.y * b.x);
}
static __device__ __forceinline__ float2 cadd(float2 a, float2 b) {
    return make_float2(a.x + b.x, a.y + b.y);
}
static __device__ __forceinline__ float2 csub(float2 a, float2 b) {
    return make_float2(a.x - b.x, a.y - b.y);
}

static __device__ __forceinline__ void barsync(int id, int nthr) {
    asm volatile("bar.sync %0, %1;" :: "r"(id), "r"(nthr) : "memory");
}

// PDL intrinsics via PTX (robust across header versions)
static __device__ __forceinline__ void pdl_trigger() {
    asm volatile("griddepcontrol.launch_dependents;");
}
static __device__ __forceinline__ void pdl_wait() {
    asm volatile("griddepcontrol.wait;" ::: "memory");
}

// packed f32x2 ops (sm_103a; FFMA2 only reachable via PTX)
#define F2ADD(d,a,b)   asm("add.rn.f32x2 %0,%1,%2;"    : "=l"(d) : "l"(a), "l"(b))
#define F2MUL(d,a,b)   asm("mul.rn.f32x2 %0,%1,%2;"    : "=l"(d) : "l"(a), "l"(b))
#define F2FMA(d,a,b,c) asm("fma.rn.f32x2 %0,%1,%2,%3;" : "=l"(d) : "l"(a), "l"(b), "l"(c))
#define F2PACK(d,lo,hi) asm("mov.b64 %0,{%1,%2};" : "=l"(d) : "f"(lo), "f"(hi))
#define F2UNPK(lo,hi,v) asm("mov.b64 {%0,%1},%2;" : "=f"(lo), "=f"(hi) : "l"(v))
#define FRCP(d,a)      asm("rcp.approx.f32 %0,%1;" : "=f"(d) : "f"(a))

// Triple-pad smem addressing: conflict-free for strides 256, 16, 1.
#define PIDX(a) ((a) + ((a) >> 4) + ((a) >> 8))

// radix-16 digit reversal for N=4096 (digits 16,16,16)
static __device__ __forceinline__ int rev16(int k) {
    return ((k & 15) << 8) | (k & 240) | (k >> 8);
}
// mixed-radix (8,16,16) un-reversal for the 2048 FFT: natural l -> position
static __device__ __forceinline__ int unrev2048(int l) {
    return ((l & 7) << 8) | (((l >> 3) & 15) << 4) | ((l >> 7) & 15);
}

// output slot permutation of bfly16: X[q] lives in v[PERM16(q)]
#define PERM16(q) ((((q) & 3) << 2) | ((q) >> 2))

// ---------------------------------------------------------------------------
template<bool INV>
static __device__ __forceinline__ void dft4(float2& a, float2& b, float2& c, float2& d)
{
    float2 t0 = cadd(a, c), t1 = csub(a, c), t2 = cadd(b, d), t3 = csub(b, d);
    float2 j3 = INV ? make_float2(-t3.y, t3.x) : make_float2(t3.y, -t3.x);
    a = cadd(t0, t2); c = csub(t0, t2);
    b = cadd(t1, j3); d = csub(t1, j3);
}

template<bool INV>
static __device__ __forceinline__ float2 cmulw(float2 x, float wr, float wi)
{
    return cmul(x, make_float2(wr, INV ? -wi : wi));
}

template<bool INV>
static __device__ __forceinline__ void bfly16(float2 v[16])
{
    const float C1 = 0.9238795325112867f, S1 = 0.3826834323650898f, R2 = 0.7071067811865476f;
    dft4<INV>(v[0], v[4], v[8],  v[12]);
    dft4<INV>(v[1], v[5], v[9],  v[13]);
    dft4<INV>(v[2], v[6], v[10], v[14]);
    dft4<INV>(v[3], v[7], v[11], v[15]);
    v[5]  = cmulw<INV>(v[5],  C1, -S1);
    v[6]  = cmulw<INV>(v[6],  R2, -R2);
    v[7]  = cmulw<INV>(v[7],  S1, -C1);
    v[9]  = cmulw<INV>(v[9],  R2, -R2);
    v[10] = cmulw<INV>(v[10], 0.f, -1.f);
    v[11] = cmulw<INV>(v[11], -R2, -R2);
    v[13] = cmulw<INV>(v[13], S1, -C1);
    v[14] = cmulw<INV>(v[14], -R2, -R2);
    v[15] = cmulw<INV>(v[15], -C1,  S1);
    dft4<INV>(v[0],  v[1],  v[2],  v[3]);
    dft4<INV>(v[4],  v[5],  v[6],  v[7]);
    dft4<INV>(v[8],  v[9],  v[10], v[11]);
    dft4<INV>(v[12], v[13], v[14], v[15]);
}

template<bool FREQ>
static __device__ __forceinline__ void twapply16(float2 v[16], float2 w1)
{
#define TSLOT(q) (FREQ ? (q) : PERM16(q))
    float2 w2 = cmul(w1, w1);
    v[TSLOT(1)] = cmul(v[TSLOT(1)], w1);
    v[TSLOT(2)] = cmul(v[TSLOT(2)], w2);
    float2 w3 = cmul(w2, w1);
    v[TSLOT(3)] = cmul(v[TSLOT(3)], w3);
    float2 w4 = cmul(w2, w2);
    v[TSLOT(4)] = cmul(v[TSLOT(4)], w4);
    float2 w5 = cmul(w4, w1);
    v[TSLOT(5)] = cmul(v[TSLOT(5)], w5);
    float2 w6 = cmul(w4, w2);
    v[TSLOT(6)] = cmul(v[TSLOT(6)], w6);
    float2 w7 = cmul(w4, w3);
    v[TSLOT(7)] = cmul(v[TSLOT(7)], w7);
    float2 w8 = cmul(w4, w4);
    v[TSLOT(8)]  = cmul(v[TSLOT(8)],  w8);
    v[TSLOT(9)]  = cmul(v[TSLOT(9)],  cmul(w8, w1));
    v[TSLOT(10)] = cmul(v[TSLOT(10)], cmul(w8, w2));
    v[TSLOT(11)] = cmul(v[TSLOT(11)], cmul(w8, w3));
    v[TSLOT(12)] = cmul(v[TSLOT(12)], cmul(w8, w4));
    v[TSLOT(13)] = cmul(v[TSLOT(13)], cmul(w8, w5));
    v[TSLOT(14)] = cmul(v[TSLOT(14)], cmul(w8, w6));
    v[TSLOT(15)] = cmul(v[TSLOT(15)], cmul(w8, w7));
#undef TSLOT
}

template<bool INV>
static __device__ void stage16(float2* buf, const float2* __restrict__ tw,
                               int L, int NB, int gtid, int GT)
{
    const int m = L >> 4;
    const int twstep = L2X / L;
    for (int b = gtid; b < NB; b += GT) {
        int j = b & (m - 1);
        int base = ((b - j) << 4) + j;
        float2 v[16];
        #pragma unroll
        for (int r = 0; r < 16; r++) v[r] = buf[PIDX(base + m * r)];

        if (!INV) {
            bfly16<false>(v);
            if (m > 1) {
                float2 w1 = tw[j * twstep];
                twapply16<false>(v, w1);
            }
        } else {
            if (m > 1) {
                float2 w1 = tw[j * twstep]; w1.y = -w1.y;
                twapply16<true>(v, w1);
            }
            bfly16<true>(v);
        }
        #pragma unroll
        for (int q = 0; q < 16; q++) buf[PIDX(base + m * q)] = v[PERM16(q)];
    }
}

template<bool INV>
static __device__ __forceinline__ void bfly8(float2 v[8])
{
    const float t = 0.70710678118654752f;
    float2 a0 = cadd(v[0], v[4]), a4 = csub(v[0], v[4]);
    float2 a1 = cadd(v[1], v[5]), a5 = csub(v[1], v[5]);
    float2 a2 = cadd(v[2], v[6]), a6 = csub(v[2], v[6]);
    float2 a3 = cadd(v[3], v[7]), a7 = csub(v[3], v[7]);
    float2 b0 = cadd(a0, a2), b2 = csub(a0, a2);
    float2 b1 = cadd(a1, a3), b3 = csub(a1, a3);
    float2 m4b3 = INV ? make_float2(-b3.y, b3.x) : make_float2(b3.y, -b3.x);
    v[0] = cadd(b0, b1);  v[4] = csub(b0, b1);
    v[2] = cadd(b2, m4b3); v[6] = csub(b2, m4b3);
    float2 c0 = a4;
    float2 c1 = INV ? make_float2(t * (a5.x - a5.y), t * (a5.x + a5.y))
                    : make_float2(t * (a5.x + a5.y), t * (a5.y - a5.x));
    float2 c2 = INV ? make_float2(-a6.y, a6.x) : make_float2(a6.y, -a6.x);
    float2 c3 = INV ? make_float2(-t * (a7.x + a7.y), t * (a7.x - a7.y))
                    : make_float2(t * (a7.y - a7.x), -t * (a7.x + a7.y));
    float2 d0 = cadd(c0, c2), d2 = csub(c0, c2);
    float2 d1 = cadd(c1, c3), d3 = csub(c1, c3);
    float2 m4d3 = INV ? make_float2(-d3.y, d3.x) : make_float2(d3.y, -d3.x);
    v[1] = cadd(d0, d1);  v[5] = csub(d0, d1);
    v[3] = cadd(d2, m4d3); v[7] = csub(d2, m4d3);
}

template<bool INV>
static __device__ void stage8(float2* buf, const float2* __restrict__ tw,
                              int L, int NB, int gtid, int GT)
{
    int m = L >> 3;
    int twstep = L2X / L;
    for (int b = gtid; b < NB; b += GT) {
        int j = b & (m - 1);
        int base = ((b - j) << 3) + j;
        float2 v[8];
        #pragma unroll
        for (int r = 0; r < 8; r++) v[r] = buf[PIDX(base + m * r)];

        if (m > 1) {
            float2 w = tw[j * twstep];
            if (INV) w.y = -w.y;
            if (!INV) {
                bfly8<false>(v);
                float2 wq = w;
                v[1] = cmul(v[1], wq);
                #pragma unroll
                for (int q = 2; q < 8; q++) { wq = cmul(wq, w); v[q] = cmul(v[q], wq); }
            } else {
                float2 wq = w;
                v[1] = cmul(v[1], wq);
                #pragma unroll
                for (int q = 2; q < 8; q++) { wq = cmul(wq, w); v[q] = cmul(v[q], wq); }
                bfly8<true>(v);
            }
        } else {
            bfly8<INV>(v);
        }
        #pragma unroll
        for (int r = 0; r < 8; r++) buf[PIDX(base + m * r)] = v[r];
    }
}

// ---------------------------------------------------------------------------
// Stage A: at_roots via Woodbury + half-angle identity (R13/R15 baseline).
// ---------------------------------------------------------------------------
__global__ __launch_bounds__(256, 4)
void at_roots_kernel(const float* __restrict__ p_ri,
                     const float* __restrict__ lambda_ri,
                     const float* __restrict__ B_ri,
                     const float* __restrict__ Ct_ri,
                     const float* __restrict__ log_step)
{
    __shared__ ulonglong2 s_nl[N_STATE];
    __shared__ ull        s_lx2[N_STATE];
    __shared__ ulonglong2 s_cb[N_STATE];
    __shared__ ulonglong2 s_cp[N_STATE];
    __shared__ ulonglong2 s_pb[N_STATE];
    __shared__ ull        s_pp[N_STATE];

    int d = blockIdx.x;
    int jlo = blockIdx.y * 512;
    int tid = threadIdx.x;

    pdl_trigger();   // allow kf to launch (kf waits via griddepcontrol.wait)

    if (tid < N_STATE) {
        int n = tid;
        float pr = p_ri[2 * n], pi = p_ri[2 * n + 1];
        float2 lam = make_float2(lambda_ri[2 * n], lambda_ri[2 * n + 1]);
        float2 Bv  = make_float2(B_ri[(d * N_STATE + n) * 2], B_ri[(d * N_STATE + n) * 2 + 1]);
        float2 Ctc = make_float2(Ct_ri[(d * N_STATE + n) * 2], -Ct_ri[(d * N_STATE + n) * 2 + 1]);
        float2 CtB = cmul(Ctc, Bv);
        float2 Ctp = cmul(Ctc, make_float2(pr, pi));
        float2 pB  = cmul(make_float2(pr, -pi), Bv);
        float  pp  = pr * pr + pi * pi;
        ull a, b;
        F2PACK(a, -lam.x, -lam.x); F2PACK(b, -lam.y, -lam.y); s_nl[n] = make_ulonglong2(a, b);
        F2PACK(a, lam.x * lam.x, lam.x * lam.x); s_lx2[n] = a;
        F2PACK(a, CtB.x, CtB.x);   F2PACK(b, CtB.y, CtB.y);   s_cb[n] = make_ulonglong2(a, b);
        F2PACK(a, Ctp.x, Ctp.x);   F2PACK(b, Ctp.y, Ctp.y);   s_cp[n] = make_ulonglong2(a, b);
        F2PACK(a, pB.x,  pB.x);    F2PACK(b, pB.y,  pB.y);    s_pb[n] = make_ulonglong2(a, b);
        F2PACK(a, pp, pp);         s_pp[n] = a;
    }
    __syncthreads();

    float tos = 2.0f * __expf(-log_step[d]);

    int j0 = jlo + 2 * tid;

    float tj[2], gyv[2];
    #pragma unroll
    for (int e = 0; e < 2; e++) {
        int j = j0 + e;
        float h = (float)j * (3.14159265358979323846f / 2048.0f);
        float t = tanf(h);                   // finite at j=1024 (fp32 pi/2)
        tj[e]  = t;
        gyv[e] = -tos * t;
    }
    ull gy2;
    F2PACK(gy2, gyv[0], gyv[1]);

    ull k00x = 0, k00y = 0, k00s = 0;
    ull k01x = 0, k01y = 0, k01s = 0;
    ull k10x = 0, k10y = 0, k10s = 0;
    ull k11x = 0, k11s = 0;

    #pragma unroll 8
    for (int n = 0; n < N_STATE; n++) {
        ulonglong2 nl = s_nl[n];
        ull lx2 = s_lx2[n];
        ulonglong2 cb = s_cb[n];
        ulonglong2 cp = s_cp[n];
        ulonglong2 pb = s_pb[n];
        ull ppv = s_pp[n];
        ull dcy, m2, r, ix, t;
        F2ADD(dcy, gy2, nl.y);
        F2FMA(m2, dcy, dcy, lx2);
        float mlo, mhi, rlo, rhi;
        F2UNPK(mlo, mhi, m2);
        FRCP(rlo, mlo);
        FRCP(rhi, mhi);
        F2PACK(r, rlo, rhi);
        F2MUL(ix, nl.x, r);
        F2MUL(t,  dcy, r);
        F2FMA(k00x, cb.x, ix, k00x);
        F2FMA(k00x, cb.y, t,  k00x);
        F2FMA(k00y, cb.y, ix, k00y);
        F2FMA(k00s, cb.x, t,  k00s);
        F2FMA(k01x, cp.x, ix, k01x);
        F2FMA(k01x, cp.y, t,  k01x);
        F2FMA(k01y, cp.y, ix, k01y);
        F2FMA(k01s, cp.x, t,  k01s);
        F2FMA(k10x, pb.x, ix, k10x);
        F2FMA(k10x, pb.y, t,  k10x);
        F2FMA(k10y, pb.y, ix, k10y);
        F2FMA(k10s, pb.x, t,  k10s);
        F2FMA(k11x, ppv, ix, k11x);
        F2FMA(k11s, ppv, t,  k11s);
    }

    float a00x[2], a00y[2], a01x[2], a01y[2], a10x[2], a10y[2], a11x[2], a11y[2];
    F2UNPK(a00x[0], a00x[1], k00x);
    { float y0,y1,s0,s1; F2UNPK(y0,y1,k00y); F2UNPK(s0,s1,k00s); a00y[0]=y0-s0; a00y[1]=y1-s1; }
    F2UNPK(a01x[0], a01x[1], k01x);
    { float y0,y1,s0,s1; F2UNPK(y0,y1,k01y); F2UNPK(s0,s1,k01s); a01y[0]=y0-s0; a01y[1]=y1-s1; }
    F2UNPK(a10x[0], a10x[1], k10x);
    { float y0,y1,s0,s1; F2UNPK(y0,y1,k10y); F2UNPK(s0,s1,k10s); a10y[0]=y0-s0; a10y[1]=y1-s1; }
    F2UNPK(a11x[0], a11x[1], k11x);
    { float s0,s1; F2UNPK(s0,s1,k11s); a11y[0]=-s0; a11y[1]=-s1; }

    float4 outv;
    #pragma unroll
    for (int e = 0; e < 2; e++) {
        float2 k00 = make_float2(a00x[e], a00y[e]);
        float2 k01 = make_float2(a01x[e], a01y[e]);
        float2 k10 = make_float2(a10x[e], a10y[e]);
        float2 den = make_float2(1.0f + a11x[e], a11y[e]);
        float rd = __fdividef(1.0f, den.x * den.x + den.y * den.y);
        float2 iden = make_float2(den.x * rd, -den.y * rd);
        float2 frac = cmul(cmul(k01, k10), iden);
        float2 z = csub(k00, frac);
        float2 res = make_float2(z.x + tj[e] * z.y, z.y - tj[e] * z.x);
        if (e == 0) { outv.x = res.x; outv.y = res.y; }
        else        { outv.z = res.x; outv.w = res.y; }
    }
    *(float4*)&g_at[d * LSEQ + j0] = outv;
}

// ---------------------------------------------------------------------------
// Stage B (split-bin form, R12/R15 baseline) + PDL: waits for at_roots only
// after its independent twiddle-gen preamble; triggers conv's early launch.
// ---------------------------------------------------------------------------
__global__ void kf_kernel(const float* __restrict__ Dp)
{
    extern __shared__ float2 sm[];
    float2* tw   = sm;                 // 512 (W_4096^k, k<512)
    float2* bufA = sm + 512;           // padded 2048 -> 2184
    float2* bufB = sm + 512 + 2184;    // padded 2048 -> 2184

    int d = blockIdx.x;
    int tid = threadIdx.x;
    const int T = 256;

    pdl_trigger();   // allow conv to launch (conv waits before reading g_kf)

    for (int k = tid; k < 512; k += T) {
        float s, c;
        sincosf(6.283185307179586f * (float)k * (1.0f / 4096.0f), &s, &c);
        tw[k] = make_float2(c, -s);
    }

    pdl_wait();      // at_roots grid complete -> g_at visible

    for (int j = tid; j < LSEQ; j += T) bufA[PIDX(j)] = g_at[d * LSEQ + j];
    __syncthreads();

    // ---- FFT-2048 of at: radices 8,16,16 -> B (digit-reversed) ----
    stage8 <false>(bufA, tw, 2048, 256, tid, T); __syncthreads();
    stage16<false>(bufA, tw,  256, 128, tid, T); __syncthreads();
    stage16<false>(bufA, tw,   16, 128, tid, T); __syncthreads();

    // ---- twist: bufB[l] = (Re(B[l])/2048 + dp*delta0) * W_4096^l ----
    float dp = Dp[d];
    const float R2 = 0.7071067811865476f;
    #pragma unroll
    for (int t = 0; t < 4; t++) {
        float w8x = (t == 0) ? 1.0f : (t == 1) ? R2 : (t == 2) ? 0.0f : -R2;
        float w8y = (t == 0) ? 0.0f : (t == 2) ? -1.0f : -R2;
        for (int l2 = tid; l2 < 512; l2 += T) {
            int l = t * 512 + l2;
            int p = unrev2048(l);
            float kr = bufA[PIDX(p)].x * (1.0f / (float)LSEQ);
            if (l == 0) kr += dp;
            float2 w = cmul(tw[l2], make_float2(w8x, w8y));
            bufB[PIDX(l)] = make_float2(kr * w.x, kr * w.y);
        }
    }
    __syncthreads();

    // ---- FFT-2048 of twisted K' -> odd bins (digit-reversed) ----
    stage8 <false>(bufB, tw, 2048, 256, tid, T); __syncthreads();
    stage16<false>(bufB, tw,  256, 128, tid, T); __syncthreads();
    stage16<false>(bufB, tw,   16, 128, tid, T); __syncthreads();

    // ---- write even (closed form) + odd together as float4 ----
    const float invN = 1.0f / (float)L2X;
    for (int m = tid; m < LSEQ; m += T) {
        float2 a1 = g_at[d * LSEQ + ((LSEQ - m) & (LSEQ - 1))];
        float2 a2 = g_at[d * LSEQ + m];
        float ex = (dp + 0.5f * (a1.x + a2.x)) * invN;
        float ey = 0.5f * (a1.y - a2.y) * invN;
        float2 Dm = bufB[PIDX(unrev2048(m))];
        *(float4*)&g_kf[(size_t)d * L2X + 2 * m] =
            make_float4(ex, ey, Dm.x * invN, Dm.y * invN);
    }
}

// ---------------------------------------------------------------------------
// Stage C: causal FFT conv (R15 baseline) + PDL: the whole preamble (u load,
// zero-pad, 3 forward stages) runs overlapped with kf; griddepcontrol.wait
// sits right before the first g_kf read.
// ---------------------------------------------------------------------------
__global__ __launch_bounds__(256, 3)
void conv_kernel(const float* __restrict__ u,
                 float* __restrict__ y)
{
    extern __shared__ float2 sm[];
    float2* tw   = sm;                        // 256 (W_4096^k, k<256)
    float2* buf0 = sm + 256;
    float2* buf1 = sm + 256 + 4368;

    int tid = threadIdx.x;
    int q   = tid >> 7;
    int gt  = tid & 127;
    float2* buf = q ? buf1 : buf0;

    int b  = blockIdx.x >> 6;
    int cb = (blockIdx.x & 63) * 4;
    int c0 = cb + 2 * q;
    int barId = 1 + q;

    pdl_trigger();   // no successor in-flight, harmless

    if (tid < 256) {
        float s, c;
        sincosf(6.283185307179586f * (float)tid * (1.0f / 4096.0f), &s, &c);
        tw[tid] = make_float2(c, -s);
    }

    const float4* ub4 = (const float4*)(u + (size_t)b * LSEQ * D_MODEL + cb);
    float4*       yb4 = (float4*)(y + (size_t)b * LSEQ * D_MODEL + cb);

    for (int l = tid; l < LSEQ; l += 256) {
        float4 f = ub4[(size_t)l * (D_MODEL / 4)];
        buf0[PIDX(l)] = make_float2(f.x, f.y);
        buf1[PIDX(l)] = make_float2(f.z, f.w);
    }
    for (int l = LSEQ + tid; l < L2X; l += 256) {
        buf0[PIDX(l)] = make_float2(0.0f, 0.0f);
        buf1[PIDX(l)] = make_float2(0.0f, 0.0f);
    }
    __syncthreads();

    stage16<false>(buf, tw, 4096, 256, gt, 128); barsync(barId, 128);
    stage16<false>(buf, tw,  256, 256, gt, 128); barsync(barId, 128);
    stage16<false>(buf, tw,   16, 256, gt, 128); barsync(barId, 128);

    pdl_wait();      // kf grid complete -> g_kf visible

    for (int k = gt; k <= 2048; k += 128) {
        int mk = (L2X - k) & (L2X - 1);
        int pk = PIDX(rev16(k));
        int pm = PIDX(rev16(mk));
        float2 Zk = buf[pk], Zm = buf[pm];
        float2 U0 = make_float2(0.5f * (Zk.x + Zm.x), 0.5f * (Zk.y - Zm.y));
        float2 U1 = make_float2(0.5f * (Zk.y + Zm.y), 0.5f * (Zm.x - Zk.x));
        float2 H0 = g_kf[(size_t)c0 * L2X + k];
        float2 H1 = g_kf[(size_t)(c0 + 1) * L2X + k];
        float2 Y0 = cmul(U0, H0);
        float2 Y1 = cmul(U1, H1);
        buf[pk] = make_float2(Y0.x - Y1.y, Y0.y + Y1.x);
        if (k != 0 && k != 2048)
            buf[pm] = make_float2(Y0.x + Y1.y, Y1.x - Y0.y);
    }
    barsync(barId, 128);

    stage16<true>(buf, tw,   16, 256, gt, 128); barsync(barId, 128);
    stage16<true>(buf, tw,  256, 256, gt, 128); barsync(barId, 128);
    stage16<true>(buf, tw, 4096, 256, gt, 128);
    __syncthreads();

    for (int l = tid; l < LSEQ; l += 256) {
        float2 r0 = buf0[PIDX(l)];
        float2 r1 = buf1[PIDX(l)];
        yb4[(size_t)l * (D_MODEL / 4)] = make_float4(r0.x, r0.y, r1.x, r1.y);
    }
}

// ---------------------------------------------------------------------------
extern "C" void kernel_launch(void* const* d_in, const int* in_sizes, int n_in,
                              void* d_out, int out_size)
{
    const float* u         = (const float*)d_in[0];
    const float* p_ri      = (const float*)d_in[1];
    const float* lambda_ri = (const float*)d_in[2];
    const float* B_ri      = (const float*)d_in[3];
    const float* Ct_ri     = (const float*)d_in[4];
    const float* Dp        = (const float*)d_in[5];
    const float* log_step  = (const float*)d_in[6];
    float* y = (float*)d_out;

    (void)in_sizes; (void)n_in; (void)out_size;

    const int KF_SMEM   = (512 + 2184 + 2184) * sizeof(float2);   // 39040
    const int CONV_SMEM = (256 + 2 * 4368) * sizeof(float2);      // 71936

    cudaFuncSetAttribute(kf_kernel,   cudaFuncAttributeMaxDynamicSharedMemorySize, KF_SMEM);
    cudaFuncSetAttribute(conv_kernel, cudaFuncAttributeMaxDynamicSharedMemorySize, CONV_SMEM);

    at_roots_kernel<<<dim3(D_MODEL, 4), 256>>>(p_ri, lambda_ri, B_ri, Ct_ri, log_step);

    // kf: PDL secondary of at_roots
    {
        cudaLaunchConfig_t cfg = {};
        cfg.gridDim = dim3(D_MODEL, 1, 1);
        cfg.blockDim = dim3(256, 1, 1);
        cfg.dynamicSmemBytes = KF_SMEM;
        cfg.stream = 0;
        cudaLaunchAttribute attr[1];
        attr[0].id = cudaLaunchAttributeProgrammaticStreamSerialization;
        attr[0].val.programmaticStreamSerializationAllowed = 1;
        cfg.attrs = attr;
        cfg.numAttrs = 1;
        cudaLaunchKernelEx(&cfg, kf_kernel, Dp);
    }

    // conv: PDL secondary of kf (preamble overlaps kf execution)
    {
        cudaLaunchConfig_t cfg = {};
        cfg.gridDim = dim3(NBATCH * 64, 1, 1);
        cfg.blockDim = dim3(256, 1, 1);
        cfg.dynamicSmemBytes = CONV_SMEM;
        cfg.stream = 0;
        cudaLaunchAttribute attr[1];
        attr[0].id = cudaLaunchAttributeProgrammaticStreamSerialization;
        attr[0].val.programmaticStreamSerializationAllowed = 1;
        cfg.attrs = attr;
        cfg.numAttrs = 1;
        cudaLaunchKernelEx(&cfg, conv_kernel, u, y);
    }
}